// round 9
// baseline (speedup 1.0000x reference)
#include <cuda_runtime.h>
#include <cuda_bf16.h>
#include <stdint.h>
#include <math.h>

// ---------------- problem constants ----------------
#define GSIZE   8
#define IDIM    1024
#define ODIM    1024
#define BATCH   4096

#define KDIM8   (2 * GSIZE * IDIM)  // 16384 int8 trig features
#define KDIMB   (3 * IDIM)          // 3072 bf16 base features (hi, lo, hi)

// ---------------- GEMM tiling (shared) ----------------
#define BM      128
#define BN      128
#define STAGES  3
#define NTH     128                 // 4 warps: 2 (m) x 2 (n), warp tile 64x64

#define TILE_BYTES   (BM * 128)                   // 16 KB (both A and B, both dtypes)
#define STAGE_BYTES  (2 * TILE_BYTES)             // 32768
#define SMEM_BYTES   (1024 + STAGES * STAGE_BYTES) // 99328 -> 2 CTAs/SM

#define NKC8    (KDIM8 / 128)       // 128 int8 chunks (128 B = 128 k)
#define NKCB    (KDIMB / 64)        // 48 bf16 chunks (128 B = 64 k)

// ---------------- scratch (no allocs allowed) ----------------
__device__ __align__(1024) int8_t        g_A8[(size_t)BATCH * KDIM8];  // 64 MB
__device__ __align__(1024) __nv_bfloat16 g_Ab[(size_t)BATCH * KDIMB];  // 24 MB
__device__ __align__(1024) int8_t        g_W8[(size_t)ODIM  * KDIM8];  // 16 MB
__device__ __align__(1024) __nv_bfloat16 g_Wb[(size_t)ODIM  * KDIMB];  //  6 MB
__device__ float g_ws[ODIM];                                           // per-o dequant

// ---------------- PTX helpers (base-arch only: sm_80-level) ----------------
__device__ __forceinline__ uint32_t smem_u32(const void* p) {
    uint32_t a;
    asm("{ .reg .u64 t; cvta.to.shared.u64 t, %1; cvt.u32.u64 %0, t; }" : "=r"(a) : "l"(p));
    return a;
}

__device__ __forceinline__ void cp16(uint32_t s, const void* g) {
    asm volatile("cp.async.cg.shared.global [%0], [%1], 16;" :: "r"(s), "l"(g) : "memory");
}
#define CP_COMMIT() asm volatile("cp.async.commit_group;" ::: "memory")
#define CP_WAIT(n)  asm volatile("cp.async.wait_group %0;" :: "n"(n) : "memory")

__device__ __forceinline__ void ldsm_x4(uint32_t* r, uint32_t addr) {
    asm volatile("ldmatrix.sync.aligned.m8n8.x4.shared.b16 {%0,%1,%2,%3}, [%4];"
                 : "=r"(r[0]), "=r"(r[1]), "=r"(r[2]), "=r"(r[3]) : "r"(addr));
}

__device__ __forceinline__ void mma16816(float* d, const uint32_t* a, uint32_t b0, uint32_t b1) {
    asm volatile("mma.sync.aligned.m16n8k16.row.col.f32.bf16.bf16.f32 "
                 "{%0,%1,%2,%3}, {%4,%5,%6,%7}, {%8,%9}, {%0,%1,%2,%3};"
                 : "+f"(d[0]), "+f"(d[1]), "+f"(d[2]), "+f"(d[3])
                 : "r"(a[0]), "r"(a[1]), "r"(a[2]), "r"(a[3]), "r"(b0), "r"(b1));
}

__device__ __forceinline__ void mma16832i(int* d, const uint32_t* a, uint32_t b0, uint32_t b1) {
    asm volatile("mma.sync.aligned.m16n8k32.row.col.s32.s8.s8.s32 "
                 "{%0,%1,%2,%3}, {%4,%5,%6,%7}, {%8,%9}, {%0,%1,%2,%3};"
                 : "+r"(d[0]), "+r"(d[1]), "+r"(d[2]), "+r"(d[3])
                 : "r"(a[0]), "r"(a[1]), "r"(a[2]), "r"(a[3]), "r"(b0), "r"(b1));
}

// ---------------- kernel 1: features ----------------
// int8 plane: k = g*IDIM+i -> round(127*cos((g+1)x)); k = (8+g)*IDIM+i -> sin
// bf16 plane: k = i -> silu_hi; IDIM+i -> silu_lo; 2*IDIM+i -> silu_hi
__global__ void __launch_bounds__(256) kan_features(const float* __restrict__ x) {
    int idx = blockIdx.x * blockDim.x + threadIdx.x;     // b*IDIM + i
    if (idx >= BATCH * IDIM) return;
    int b = idx >> 10, i = idx & (IDIM - 1);
    float v = x[idx];

    float s1, c1;
    __sincosf(v, &s1, &c1);     // |err| ~1e-6; int8 quant (3.9e-3) dominates
    int8_t* d8 = g_A8 + (size_t)b * KDIM8 + i;

    float ck = c1, sk = s1;
#pragma unroll
    for (int g = 0; g < GSIZE; g++) {
        if (g) {
            float cn = ck * c1 - sk * s1;   // exact angle-addition recurrence
            float sn = sk * c1 + ck * s1;
            ck = cn; sk = sn;
        }
        d8[g * IDIM]           = (int8_t)__float2int_rn(fminf(fmaxf(ck, -1.f), 1.f) * 127.f);
        d8[(GSIZE + g) * IDIM] = (int8_t)__float2int_rn(fminf(fmaxf(sk, -1.f), 1.f) * 127.f);
    }

    float sig = 1.0f / (1.0f + __expf(-v));
    float su  = v * sig;                             // silu(x)
    __nv_bfloat16 hi = __float2bfloat16_rn(su);
    float lo = su - __bfloat162float(hi);
    __nv_bfloat16* db = g_Ab + (size_t)b * KDIMB + i;
    db[0 * IDIM] = hi;
    db[1 * IDIM] = __float2bfloat16_rn(lo);
    db[2 * IDIM] = hi;
}

// ---------------- kernel 2: pack weights (one block per output row o) ----------------
// int8 plane with per-row scale; bf16 hi/lo plane for base.
__global__ void __launch_bounds__(256) kan_pack(const float* __restrict__ scale_base,
                                                const float* __restrict__ scale_spline,
                                                const float* __restrict__ coeff) {
    extern __shared__ float wsm[];                 // KDIM8 floats + 256 reduce slots
    float* red = wsm + KDIM8;
    int o = blockIdx.x, tid = threadIdx.x;

    float amax = 0.f;
#pragma unroll
    for (int t = 0; t < 4; t++) {
        int i = tid * 4 + t;
        float ss = scale_spline[o * IDIM + i];
        const float* c0 = coeff + ((size_t)o * IDIM + i) * GSIZE;
        const float* c1 = c0 + (size_t)ODIM * IDIM * GSIZE;
#pragma unroll
        for (int g = 0; g < GSIZE; g++) {
            float w0 = ss * c0[g], w1 = ss * c1[g];
            wsm[g * IDIM + i]           = w0;
            wsm[(GSIZE + g) * IDIM + i] = w1;
            amax = fmaxf(amax, fmaxf(fabsf(w0), fabsf(w1)));
        }
        // base plane (independent of spline scale)
        float sb = scale_base[o * IDIM + i];
        __nv_bfloat16 bh = __float2bfloat16_rn(sb);
        float bl = sb - __bfloat162float(bh);
        __nv_bfloat16* db = g_Wb + (size_t)o * KDIMB + i;
        db[0 * IDIM] = bh;
        db[1 * IDIM] = bh;
        db[2 * IDIM] = __float2bfloat16_rn(bl);
    }
    red[tid] = amax;
    __syncthreads();
    for (int s = 128; s > 0; s >>= 1) {
        if (tid < s) red[tid] = fmaxf(red[tid], red[tid + s]);
        __syncthreads();
    }
    float mx  = fmaxf(red[0], 1e-30f);
    float inv = 127.f / mx;
    if (tid == 0) g_ws[o] = mx / (127.f * 127.f);  // dequant = qa*qw*g_ws

    int8_t* dst = g_W8 + (size_t)o * KDIM8;
    for (int j = tid; j < KDIM8; j += 256) {
        float q = wsm[j] * inv;
        dst[j] = (int8_t)__float2int_rn(fminf(fmaxf(q, -127.f), 127.f));
    }
}

// ---------------- stage loader (16 KB + 16 KB, 128B rows) ----------------
__device__ __forceinline__ void load_stage(uint32_t sA, uint32_t sB,
                                           const char* gA, const char* gB,
                                           size_t rowb, int tid) {
#pragma unroll
    for (int t = 0; t < 8; t++) {
        int c = tid + t * NTH;
        int row = c >> 3, colb = (c & 7) * 16;
        uint32_t so = sA + row * 128 + (colb ^ ((row & 7) * 16));
        cp16(so, gA + (size_t)row * rowb + colb);
    }
#pragma unroll
    for (int t = 0; t < 8; t++) {
        int c = tid + t * NTH;
        int row = c >> 3, colb = (c & 7) * 16;
        uint32_t so = sB + row * 128 + (colb ^ ((row & 7) * 16));
        cp16(so, gB + (size_t)row * rowb + colb);
    }
}

// ---------------- kernel 3: int8 spline GEMM (writes out) ----------------
__global__ void __launch_bounds__(NTH, 2)
kan_gemm_s8(float* __restrict__ out) {
    extern __shared__ char smem_raw[];
    uint32_t sbase = (smem_u32(smem_raw) + 1023u) & ~1023u;

    int tid  = threadIdx.x;
    int lane = tid & 31, wid = tid >> 5;
    int wm = wid & 1, wn = wid >> 1;
    int mt  = blockIdx.x & 31;
    int ntb = blockIdx.x >> 5;

    const char* gA0 = (const char*)(g_A8 + (size_t)(mt * BM) * KDIM8);
    const char* gB0 = (const char*)(g_W8 + (size_t)(ntb * BN) * KDIM8);

#pragma unroll
    for (int s = 0; s < STAGES - 1; s++) {
        uint32_t st = sbase + s * STAGE_BYTES;
        load_stage(st, st + TILE_BYTES, gA0 + s * 128, gB0 + s * 128, KDIM8, tid);
        CP_COMMIT();
    }

    int acc[4][8][4];
#pragma unroll
    for (int a = 0; a < 4; a++)
#pragma unroll
        for (int b = 0; b < 8; b++)
#pragma unroll
            for (int c = 0; c < 4; c++) acc[a][b][c] = 0;

    int laA = lane & 15;
    int lcA = (lane >> 4) * 16;
    int bjj = lane >> 3;
    int laB = ((bjj >> 1) << 3) + (lane & 7);
    int lcB = (bjj & 1) * 16;

    int sc = 0, sl = STAGES - 1;
    for (int kc = 0; kc < NKC8; kc++) {
        CP_WAIT(STAGES - 2);
        __syncthreads();

        int lkc = kc + STAGES - 1;
        if (lkc < NKC8) {
            uint32_t st = sbase + sl * STAGE_BYTES;
            load_stage(st, st + TILE_BYTES, gA0 + (size_t)lkc * 128,
                       gB0 + (size_t)lkc * 128, KDIM8, tid);
        }
        CP_COMMIT();
        sl = (sl + 1 == STAGES) ? 0 : sl + 1;

        uint32_t sA = sbase + sc * STAGE_BYTES;
        uint32_t sB = sA + TILE_BYTES;
        sc = (sc + 1 == STAGES) ? 0 : sc + 1;

#pragma unroll
        for (int ks = 0; ks < 4; ks++) {       // 4 x k32 (32B) per 128B chunk
            uint32_t af[4][4];
#pragma unroll
            for (int m2 = 0; m2 < 4; m2++) {
                int row = wm * 64 + m2 * 16 + laA;
                uint32_t addr = sA + row * 128 + ((ks * 32 + lcA) ^ ((row & 7) * 16));
                ldsm_x4(af[m2], addr);
            }
            uint32_t bf[4][4];
#pragma unroll
            for (int n2 = 0; n2 < 4; n2++) {
                int row = wn * 64 + n2 * 16 + laB;
                uint32_t addr = sB + row * 128 + ((ks * 32 + lcB) ^ ((row & 7) * 16));
                ldsm_x4(bf[n2], addr);
            }
#pragma unroll
            for (int m2 = 0; m2 < 4; m2++)
#pragma unroll
                for (int n2 = 0; n2 < 4; n2++) {
                    mma16832i(acc[m2][n2 * 2],     af[m2], bf[n2][0], bf[n2][1]);
                    mma16832i(acc[m2][n2 * 2 + 1], af[m2], bf[n2][2], bf[n2][3]);
                }
        }
    }

    // ---- epilogue: dequant + write ----
    int r0 = mt * BM + wm * 64;
    int c0 = ntb * BN + wn * 64;
    float ws0[8], ws1[8];
#pragma unroll
    for (int n8 = 0; n8 < 8; n8++) {
        int c = c0 + n8 * 8 + (lane & 3) * 2;
        ws0[n8] = g_ws[c];
        ws1[n8] = g_ws[c + 1];
    }
#pragma unroll
    for (int m2 = 0; m2 < 4; m2++)
#pragma unroll
        for (int rr = 0; rr < 2; rr++) {
            int row = r0 + m2 * 16 + rr * 8 + (lane >> 2);
            float* orow = out + (size_t)row * ODIM + c0 + (lane & 3) * 2;
#pragma unroll
            for (int n8 = 0; n8 < 8; n8++) {
                float2 v = make_float2((float)acc[m2][n8][rr * 2] * ws0[n8],
                                       (float)acc[m2][n8][rr * 2 + 1] * ws1[n8]);
                *(float2*)(orow + n8 * 8) = v;
            }
        }
}

// ---------------- kernel 4: bf16 base GEMM (accumulates into out) ----------------
__global__ void __launch_bounds__(NTH, 2)
kan_gemm_base(float* __restrict__ out) {
    extern __shared__ char smem_raw[];
    uint32_t sbase = (smem_u32(smem_raw) + 1023u) & ~1023u;

    int tid  = threadIdx.x;
    int lane = tid & 31, wid = tid >> 5;
    int wm = wid & 1, wn = wid >> 1;
    int mt  = blockIdx.x & 31;
    int ntb = blockIdx.x >> 5;

    const char* gA0 = (const char*)(g_Ab + (size_t)(mt * BM) * KDIMB);
    const char* gB0 = (const char*)(g_Wb + (size_t)(ntb * BN) * KDIMB);

#pragma unroll
    for (int s = 0; s < STAGES - 1; s++) {
        uint32_t st = sbase + s * STAGE_BYTES;
        load_stage(st, st + TILE_BYTES, gA0 + s * 128, gB0 + s * 128, KDIMB * 2, tid);
        CP_COMMIT();
    }

    float acc[4][8][4];
#pragma unroll
    for (int a = 0; a < 4; a++)
#pragma unroll
        for (int b = 0; b < 8; b++)
#pragma unroll
            for (int c = 0; c < 4; c++) acc[a][b][c] = 0.f;

    int laA = lane & 15;
    int lcA = (lane >> 4) * 16;
    int bjj = lane >> 3;
    int laB = ((bjj >> 1) << 3) + (lane & 7);
    int lcB = (bjj & 1) * 16;

    int sc = 0, sl = STAGES - 1;
    for (int kc = 0; kc < NKCB; kc++) {
        CP_WAIT(STAGES - 2);
        __syncthreads();

        int lkc = kc + STAGES - 1;
        if (lkc < NKCB) {
            uint32_t st = sbase + sl * STAGE_BYTES;
            load_stage(st, st + TILE_BYTES, gA0 + (size_t)lkc * 128,
                       gB0 + (size_t)lkc * 128, KDIMB * 2, tid);
        }
        CP_COMMIT();
        sl = (sl + 1 == STAGES) ? 0 : sl + 1;

        uint32_t sA = sbase + sc * STAGE_BYTES;
        uint32_t sB = sA + TILE_BYTES;
        sc = (sc + 1 == STAGES) ? 0 : sc + 1;

#pragma unroll
        for (int ks = 0; ks < 4; ks++) {       // 4 x k16 (32B) per 128B chunk
            uint32_t af[4][4];
#pragma unroll
            for (int m2 = 0; m2 < 4; m2++) {
                int row = wm * 64 + m2 * 16 + laA;
                uint32_t addr = sA + row * 128 + ((ks * 32 + lcA) ^ ((row & 7) * 16));
                ldsm_x4(af[m2], addr);
            }
            uint32_t bf[4][4];
#pragma unroll
            for (int n2 = 0; n2 < 4; n2++) {
                int row = wn * 64 + n2 * 16 + laB;
                uint32_t addr = sB + row * 128 + ((ks * 32 + lcB) ^ ((row & 7) * 16));
                ldsm_x4(bf[n2], addr);
            }
#pragma unroll
            for (int m2 = 0; m2 < 4; m2++)
#pragma unroll
                for (int n2 = 0; n2 < 4; n2++) {
                    mma16816(acc[m2][n2 * 2],     af[m2], bf[n2][0], bf[n2][1]);
                    mma16816(acc[m2][n2 * 2 + 1], af[m2], bf[n2][2], bf[n2][3]);
                }
        }
    }

    // ---- epilogue: out += base ----
    int r0 = mt * BM + wm * 64;
    int c0 = ntb * BN + wn * 64;
#pragma unroll
    for (int m2 = 0; m2 < 4; m2++)
#pragma unroll
        for (int rr = 0; rr < 2; rr++) {
            int row = r0 + m2 * 16 + rr * 8 + (lane >> 2);
            float* orow = out + (size_t)row * ODIM + c0 + (lane & 3) * 2;
#pragma unroll
            for (int n8 = 0; n8 < 8; n8++) {
                float2 v = *(float2*)(orow + n8 * 8);
                v.x += acc[m2][n8][rr * 2];
                v.y += acc[m2][n8][rr * 2 + 1];
                *(float2*)(orow + n8 * 8) = v;
            }
        }
}

// ---------------- host launch ----------------
extern "C" void kernel_launch(void* const* d_in, const int* in_sizes, int n_in,
                              void* d_out, int out_size) {
    const float* x            = (const float*)d_in[0];
    const float* scale_base   = (const float*)d_in[1];
    const float* scale_spline = (const float*)d_in[2];
    const float* coeff        = (const float*)d_in[3];
    float* out = (float*)d_out;

    int pack_smem = KDIM8 * sizeof(float) + 256 * sizeof(float);   // 66560
    cudaFuncSetAttribute(kan_pack,      cudaFuncAttributeMaxDynamicSharedMemorySize, pack_smem);
    cudaFuncSetAttribute(kan_gemm_s8,   cudaFuncAttributeMaxDynamicSharedMemorySize, SMEM_BYTES);
    cudaFuncSetAttribute(kan_gemm_base, cudaFuncAttributeMaxDynamicSharedMemorySize, SMEM_BYTES);

    kan_features<<<(BATCH * IDIM) / 256, 256>>>(x);
    kan_pack<<<ODIM, 256, pack_smem>>>(scale_base, scale_spline, coeff);
    kan_gemm_s8<<<(BATCH / BM) * (ODIM / BN), NTH, SMEM_BYTES>>>(out);
    kan_gemm_base<<<(BATCH / BM) * (ODIM / BN), NTH, SMEM_BYTES>>>(out);
}

// round 10
// speedup vs baseline: 3.1302x; 3.1302x over previous
#include <cuda_runtime.h>
#include <cuda_bf16.h>
#include <stdint.h>
#include <math.h>

// ---------------- problem constants ----------------
#define GSIZE   8
#define IDIM    1024
#define ODIM    1024
#define BATCH   4096
#define NF      19                  // 8 cos + 8 sin + 3 base-split features
#define KDIM    (NF * IDIM)         // 19456

// ---------------- GEMM tiling ----------------
#define BM      128
#define BN      128
#define BK      64                  // K per pipeline stage (128B rows)
#define NKC     (KDIM / BK)         // 304
#define STAGES  3
#define NTH     128                 // 4 warps: 2 (m) x 2 (n), warp tile 64x64

#define A_TILE_BYTES (BM * BK * 2)            // 16384
#define B_TILE_BYTES (BN * BK * 2)            // 16384
#define STAGE_BYTES  (A_TILE_BYTES + B_TILE_BYTES) // 32768
#define SMEM_BYTES   (1024 + STAGES * STAGE_BYTES) // 99328 -> 2 CTAs/SM

#define ROWB         (KDIM * 2)     // gmem row stride in bytes (38912, 16B-aligned)

// ---------------- scratch (no allocs allowed) ----------------
__device__ __align__(1024) __nv_bfloat16 g_A[(size_t)BATCH * KDIM]; // ~152 MB
__device__ __align__(1024) __nv_bfloat16 g_W[(size_t)ODIM  * KDIM]; // ~40 MB

// ---------------- PTX helpers (base-arch only: sm_80-level) ----------------
__device__ __forceinline__ uint32_t smem_u32(const void* p) {
    uint32_t a;
    asm("{ .reg .u64 t; cvta.to.shared.u64 t, %1; cvt.u32.u64 %0, t; }" : "=r"(a) : "l"(p));
    return a;
}

__device__ __forceinline__ void cp16(uint32_t s, const void* g) {
    asm volatile("cp.async.cg.shared.global [%0], [%1], 16;" :: "r"(s), "l"(g) : "memory");
}
#define CP_COMMIT() asm volatile("cp.async.commit_group;" ::: "memory")
#define CP_WAIT(n)  asm volatile("cp.async.wait_group %0;" :: "n"(n) : "memory")

__device__ __forceinline__ void ldsm_x4(uint32_t* r, uint32_t addr) {
    asm volatile("ldmatrix.sync.aligned.m8n8.x4.shared.b16 {%0,%1,%2,%3}, [%4];"
                 : "=r"(r[0]), "=r"(r[1]), "=r"(r[2]), "=r"(r[3]) : "r"(addr));
}

__device__ __forceinline__ void mma16816(float* d, const uint32_t* a, uint32_t b0, uint32_t b1) {
    asm volatile("mma.sync.aligned.m16n8k16.row.col.f32.bf16.bf16.f32 "
                 "{%0,%1,%2,%3}, {%4,%5,%6,%7}, {%8,%9}, {%0,%1,%2,%3};"
                 : "+f"(d[0]), "+f"(d[1]), "+f"(d[2]), "+f"(d[3])
                 : "r"(a[0]), "r"(a[1]), "r"(a[2]), "r"(a[3]), "r"(b0), "r"(b1));
}

// ---------------- kernel 1: feature matrix F[b, k] ----------------
// k = t*IDIM + i; t: 0..7 cos((t+1)x), 8..15 sin((t-7)x), 16 silu_hi, 17 silu_lo, 18 silu_hi
__global__ void __launch_bounds__(256) kan_features(const float* __restrict__ x) {
    int idx = blockIdx.x * blockDim.x + threadIdx.x;     // b*IDIM + i
    if (idx >= BATCH * IDIM) return;
    int b = idx >> 10, i = idx & (IDIM - 1);
    float v = x[idx];

    float s1, c1;
    __sincosf(v, &s1, &c1);     // |err| ~1e-6 over N(0,1) range; bf16 eps dominates
    __nv_bfloat16* dst = g_A + (size_t)b * KDIM + i;

    float ck = c1, sk = s1;
    dst[0 * IDIM] = __float2bfloat16_rn(ck);
    dst[8 * IDIM] = __float2bfloat16_rn(sk);
#pragma unroll
    for (int g = 1; g < GSIZE; g++) {
        float cn = ck * c1 - sk * s1;   // exact angle-addition recurrence
        float sn = sk * c1 + ck * s1;
        ck = cn; sk = sn;
        dst[g * IDIM]       = __float2bfloat16_rn(ck);
        dst[(8 + g) * IDIM] = __float2bfloat16_rn(sk);
    }

    float sig = 1.0f / (1.0f + __expf(-v));
    float su  = v * sig;                             // silu(x)
    __nv_bfloat16 hi = __float2bfloat16_rn(su);
    float lo = su - __bfloat162float(hi);
    dst[16 * IDIM] = hi;
    dst[17 * IDIM] = __float2bfloat16_rn(lo);
    dst[18 * IDIM] = hi;
}

// ---------------- kernel 2: packed weights W[o, k] ----------------
__global__ void __launch_bounds__(256) kan_pack(const float* __restrict__ scale_base,
                                                const float* __restrict__ scale_spline,
                                                const float* __restrict__ coeff) {
    int idx = blockIdx.x * blockDim.x + threadIdx.x;     // o*IDIM + i
    if (idx >= ODIM * IDIM) return;
    int o = idx >> 10, i = idx & (IDIM - 1);

    float ss = scale_spline[idx];
    __nv_bfloat16* dst = g_W + (size_t)o * KDIM + i;
    const float* c0 = coeff + ((size_t)o * IDIM + i) * GSIZE;
    const float* c1 = coeff + (size_t)ODIM * IDIM * GSIZE + ((size_t)o * IDIM + i) * GSIZE;

#pragma unroll
    for (int g = 0; g < GSIZE; g++) {
        dst[g * IDIM]       = __float2bfloat16_rn(ss * c0[g]);   // pairs with cos
        dst[(8 + g) * IDIM] = __float2bfloat16_rn(ss * c1[g]);   // pairs with sin
    }
    float sb = scale_base[idx];
    __nv_bfloat16 bh = __float2bfloat16_rn(sb);
    float bl = sb - __bfloat162float(bh);
    dst[16 * IDIM] = bh;                         // pairs with silu_hi
    dst[17 * IDIM] = bh;                         // pairs with silu_lo
    dst[18 * IDIM] = __float2bfloat16_rn(bl);    // pairs with silu_hi
}

// ---------------- kernel 3: pipelined HMMA GEMM out = F @ W^T ----------------
// 256 CTAs (32 m x 8 n), 2 CTAs/SM, 128 threads (4 warps of 64x64), 3-stage pipeline.
// cp.async issue is spread across the 4 ks-groups; co-resident CTAs (bid >= 148)
// process K-chunks offset by NKC/2 to decorrelate barrier/LSU phases.

__global__ void __launch_bounds__(NTH, 2)
kan_gemm(float* __restrict__ out) {
    extern __shared__ char smem_raw[];
    uint32_t sbase = (smem_u32(smem_raw) + 1023u) & ~1023u;

    int tid  = threadIdx.x;
    int lane = tid & 31, wid = tid >> 5;
    int wm = wid & 1, wn = wid >> 1;           // 2 x 2 warp grid, warp tile 64x64
    int mt  = blockIdx.x & 31;                 // 32 m-tiles
    int ntb = blockIdx.x >> 5;                 // 8 n-tiles
    int off = (blockIdx.x >= 148) ? (NKC / 2) : 0;   // stagger co-resident CTAs

    const char* gA0 = (const char*)(g_A + (size_t)(mt * BM) * KDIM);
    const char* gB0 = (const char*)(g_W + (size_t)(ntb * BN) * KDIM);

    // per-thread stage-load addressing (row0 = tid/8 in 0..15, +16 per sub-load)
    int r0   = tid >> 3;
    int colb = (tid & 7) * 16;
    uint32_t swc    = (uint32_t)(colb ^ ((r0 & 7) * 16));   // swizzle invariant in t
    uint32_t sA_off = (uint32_t)r0 * 128 + swc;
    size_t   g_off  = (size_t)r0 * ROWB + colb;

    // ---- prologue: fill STAGES-1 stages ----
#pragma unroll
    for (int s = 0; s < STAGES - 1; s++) {
        int c = s + off; if (c >= NKC) c -= NKC;
        uint32_t st = sbase + s * STAGE_BYTES;
        const char* ga = gA0 + (size_t)c * 128 + g_off;
        const char* gb = gB0 + (size_t)c * 128 + g_off;
#pragma unroll
        for (int t = 0; t < 8; t++) {
            cp16(st + sA_off + t * 2048,                ga + (size_t)t * (16 * ROWB));
            cp16(st + A_TILE_BYTES + sA_off + t * 2048, gb + (size_t)t * (16 * ROWB));
        }
        CP_COMMIT();
    }

    float acc[4][8][4];                        // [m16 tile][n8 tile][frag] = 128 regs
#pragma unroll
    for (int a = 0; a < 4; a++)
#pragma unroll
        for (int b = 0; b < 8; b++)
#pragma unroll
            for (int c = 0; c < 4; c++) acc[a][b][c] = 0.f;

    // per-lane ldmatrix address components
    int laA = lane & 15;                       // A row offset within m16
    int lcA = (lane >> 4) * 16;                // A col byte offset (k8 half)
    int bjj = lane >> 3;                       // B quad index
    int laB = ((bjj >> 1) << 3) + (lane & 7);  // B row offset within n16
    int lcB = (bjj & 1) * 16;                  // B col byte offset

    int sc = 0;                                // compute stage
    int sl = STAGES - 1;                       // load stage
    for (int kc = 0; kc < NKC; kc++) {
        CP_WAIT(STAGES - 2);
        __syncthreads();

        int  lkc    = kc + STAGES - 1;
        bool doload = lkc < NKC;
        int  lck    = lkc + off; if (lck >= NKC) lck -= NKC;
        uint32_t ldst = sbase + sl * STAGE_BYTES;
        const char* lga = gA0 + (size_t)lck * 128 + g_off;
        const char* lgb = gB0 + (size_t)lck * 128 + g_off;

        uint32_t sA = sbase + sc * STAGE_BYTES;
        uint32_t sB = sA + A_TILE_BYTES;

#pragma unroll
        for (int ks = 0; ks < 4; ks++) {       // 4 x k16 per stage
            uint32_t af[4][4];
#pragma unroll
            for (int m2 = 0; m2 < 4; m2++) {
                int row = wm * 64 + m2 * 16 + laA;
                uint32_t addr = sA + row * 128 + ((ks * 32 + lcA) ^ ((row & 7) * 16));
                ldsm_x4(af[m2], addr);
            }
            uint32_t bf[4][4];
#pragma unroll
            for (int n2 = 0; n2 < 4; n2++) {
                int row = wn * 64 + n2 * 16 + laB;
                uint32_t addr = sB + row * 128 + ((ks * 32 + lcB) ^ ((row & 7) * 16));
                ldsm_x4(bf[n2], addr);         // r0,r1: n0-7 (k0,k8); r2,r3: n8-15
            }
            // spread next-stage loads under the MMA block (4 of 16 per ks group)
            if (doload) {
#pragma unroll
                for (int u = 0; u < 2; u++) {
                    int t = ks * 2 + u;
                    cp16(ldst + sA_off + t * 2048,
                         lga + (size_t)t * (16 * ROWB));
                    cp16(ldst + A_TILE_BYTES + sA_off + t * 2048,
                         lgb + (size_t)t * (16 * ROWB));
                }
            }
#pragma unroll
            for (int m2 = 0; m2 < 4; m2++)
#pragma unroll
                for (int n2 = 0; n2 < 4; n2++) {
                    mma16816(acc[m2][n2 * 2],     af[m2], bf[n2][0], bf[n2][1]);
                    mma16816(acc[m2][n2 * 2 + 1], af[m2], bf[n2][2], bf[n2][3]);
                }
        }
        CP_COMMIT();
        sl = (sl + 1 == STAGES) ? 0 : sl + 1;
        sc = (sc + 1 == STAGES) ? 0 : sc + 1;
    }

    // ---- epilogue: accum regs -> gmem ----
    int r0o = mt * BM + wm * 64;
    int c0o = ntb * BN + wn * 64;
#pragma unroll
    for (int m2 = 0; m2 < 4; m2++)
#pragma unroll
        for (int rr = 0; rr < 2; rr++) {
            int row = r0o + m2 * 16 + rr * 8 + (lane >> 2);
            float* orow = out + (size_t)row * ODIM + c0o + (lane & 3) * 2;
#pragma unroll
            for (int n8 = 0; n8 < 8; n8++) {
                float2 v = make_float2(acc[m2][n8][rr * 2], acc[m2][n8][rr * 2 + 1]);
                *(float2*)(orow + n8 * 8) = v;
            }
        }
}

// ---------------- host launch ----------------
extern "C" void kernel_launch(void* const* d_in, const int* in_sizes, int n_in,
                              void* d_out, int out_size) {
    const float* x            = (const float*)d_in[0];
    const float* scale_base   = (const float*)d_in[1];
    const float* scale_spline = (const float*)d_in[2];
    const float* coeff        = (const float*)d_in[3];
    float* out = (float*)d_out;

    cudaFuncSetAttribute(kan_gemm, cudaFuncAttributeMaxDynamicSharedMemorySize, SMEM_BYTES);

    kan_features<<<(BATCH * IDIM) / 256, 256>>>(x);
    kan_pack<<<(ODIM * IDIM) / 256, 256>>>(scale_base, scale_spline, coeff);
    kan_gemm<<<(BATCH / BM) * (ODIM / BN), NTH, SMEM_BYTES>>>(out);
}